// round 2
// baseline (speedup 1.0000x reference)
#include <cuda_runtime.h>
#include <cuda_bf16.h>

#define N_GRAPHS 64
#define DIMTOT   240     // 64*1 + 32*3 + 16*5
#define NFLOAT4  60      // DIMTOT/4
#define EPS      1e-05f
#define NPW      64      // nodes per warp in stats pass

// stats layout per graph: [0]=count, [1]=s0, [2]=ss0, [3..5]=s1[d], [6..10]=s2[d]
__device__ float g_stats[N_GRAPHS][12];
__device__ float g_A[N_GRAPHS * DIMTOT];
__device__ float g_B[N_GRAPHS * DIMTOT];

__global__ void zero_stats_kernel() {
    int i = threadIdx.x;
    if (i < N_GRAPHS * 12) ((float*)g_stats)[i] = 0.0f;
}

// ---------------------------------------------------------------------------
// Pass 1: per-graph sums. One warp handles NPW consecutive nodes.
// Lane L owns columns L, L+32, ..., L+224 (k = 0..7; k=7 valid only L<16).
// Bucket of column c: c<64 -> s0/ss0 ; 64<=c<160 -> s1[(c-64)%3] ; else s2[(c-160)%5]
// Per-lane register accumulators, flushed (warp-reduce + atomicAdd) only when
// the graph id changes (batch is sorted) and at range end.
// ---------------------------------------------------------------------------
__global__ __launch_bounds__(256) void stats_kernel(const float* __restrict__ x,
                                                    const int* __restrict__ batch,
                                                    int n_nodes) {
    const int warp_id = (blockIdx.x * blockDim.x + threadIdx.x) >> 5;
    const int lane = threadIdx.x & 31;
    const int n0 = warp_id * NPW;
    if (n0 >= n_nodes) return;
    const int n1 = min(n0 + NPW, n_nodes);

    // per-lane component routing (constant over the node loop)
    int d1[3], d2[3];
#pragma unroll
    for (int k = 2; k <= 4; k++) d1[k - 2] = (lane + 32 * k - 64) % 3;
#pragma unroll
    for (int k = 5; k <= 7; k++) d2[k - 5] = (lane + 32 * k - 160) % 5;
    const bool has_k7 = (lane < 16);

    float acc[8];
#pragma unroll
    for (int k = 0; k < 8; k++) acc[k] = 0.0f;
    float accsq = 0.0f;
    float cnt = 0.0f;

    int cur_g = __ldg(&batch[n0]);

    for (int n = n0; n < n1; n++) {
        int g = __ldg(&batch[n]);
        if (g != cur_g) {
            // ---- flush ----
            float v[10];
            v[0] = acc[0] + acc[1];
            v[1] = accsq;
#pragma unroll
            for (int d = 0; d < 3; d++)
                v[2 + d] = (d1[0] == d ? acc[2] : 0.0f) +
                           (d1[1] == d ? acc[3] : 0.0f) +
                           (d1[2] == d ? acc[4] : 0.0f);
#pragma unroll
            for (int d = 0; d < 5; d++)
                v[5 + d] = (d2[0] == d ? acc[5] : 0.0f) +
                           (d2[1] == d ? acc[6] : 0.0f) +
                           ((has_k7 && d2[2] == d) ? acc[7] : 0.0f);
#pragma unroll
            for (int off = 16; off > 0; off >>= 1) {
#pragma unroll
                for (int i = 0; i < 10; i++)
                    v[i] += __shfl_xor_sync(0xFFFFFFFFu, v[i], off);
            }
            if (lane == 0) {
                atomicAdd(&g_stats[cur_g][0], cnt);
#pragma unroll
                for (int i = 0; i < 10; i++)
                    atomicAdd(&g_stats[cur_g][1 + i], v[i]);
            }
#pragma unroll
            for (int k = 0; k < 8; k++) acc[k] = 0.0f;
            accsq = 0.0f;
            cnt = 0.0f;
            cur_g = g;
        }
        const float* row = x + (size_t)n * DIMTOT;
#pragma unroll
        for (int k = 0; k < 7; k++) {
            float vv = __ldg(&row[lane + 32 * k]);
            acc[k] += vv;
            if (k < 2) accsq += vv * vv;
        }
        if (has_k7) {
            float vv = __ldg(&row[lane + 224]);
            acc[7] += vv;
        }
        cnt += 1.0f;
    }

    // final flush
    {
        float v[10];
        v[0] = acc[0] + acc[1];
        v[1] = accsq;
#pragma unroll
        for (int d = 0; d < 3; d++)
            v[2 + d] = (d1[0] == d ? acc[2] : 0.0f) +
                       (d1[1] == d ? acc[3] : 0.0f) +
                       (d1[2] == d ? acc[4] : 0.0f);
#pragma unroll
        for (int d = 0; d < 5; d++)
            v[5 + d] = (d2[0] == d ? acc[5] : 0.0f) +
                       (d2[1] == d ? acc[6] : 0.0f) +
                       ((has_k7 && d2[2] == d) ? acc[7] : 0.0f);
#pragma unroll
        for (int off = 16; off > 0; off >>= 1) {
#pragma unroll
            for (int i = 0; i < 10; i++)
                v[i] += __shfl_xor_sync(0xFFFFFFFFu, v[i], off);
        }
        if (lane == 0) {
            atomicAdd(&g_stats[cur_g][0], cnt);
#pragma unroll
            for (int i = 0; i < 10; i++)
                atomicAdd(&g_stats[cur_g][1 + i], v[i]);
        }
    }
}

// ---------------------------------------------------------------------------
// Pass 1.5: build per-(graph,column) affine params  out = x*A + B
// ---------------------------------------------------------------------------
__global__ void params_kernel(const float* __restrict__ weight,
                              const float* __restrict__ bias) {
    int idx = blockIdx.x * blockDim.x + threadIdx.x;
    if (idx >= N_GRAPHS * DIMTOT) return;
    int g = idx / DIMTOT;
    int c = idx - g * DIMTOT;

    float cntf = fmaxf(g_stats[g][0], 1.0f);
    float a, b;
    if (c < 64) {
        float inv64 = 1.0f / (cntf * 64.0f);
        float m = g_stats[g][1] * inv64;
        float var = g_stats[g][2] * inv64 - m * m;
        float inv = 1.0f / (sqrtf(fmaxf(var, 0.0f)) + EPS);
        a = weight[c] * inv;
        b = bias[c] - m * a;
    } else if (c < 160) {
        int cc = c - 64;
        int d = cc % 3;
        int mI = cc / 3;
        float mu = g_stats[g][3 + d] / (cntf * 32.0f);
        a = weight[64 + mI];
        b = -mu * a;
    } else {
        int cc = c - 160;
        int d = cc % 5;
        int mI = cc / 5;
        float mu = g_stats[g][6 + d] / (cntf * 16.0f);
        a = weight[96 + mI];
        b = -mu * a;
    }
    g_A[idx] = a;
    g_B[idx] = b;
}

// ---------------------------------------------------------------------------
// Pass 2: streaming affine apply, float4 per thread.
// ---------------------------------------------------------------------------
__global__ __launch_bounds__(256) void apply_kernel(const float* __restrict__ x,
                                                    const int* __restrict__ batch,
                                                    float* __restrict__ out,
                                                    int n_nodes) {
    int idx = blockIdx.x * blockDim.x + threadIdx.x;
    int total = n_nodes * NFLOAT4;
    if (idx >= total) return;
    int n = idx / NFLOAT4;
    int c4 = idx - n * NFLOAT4;
    int g = __ldg(&batch[n]);

    float4 xv = ((const float4*)x)[idx];
    float4 av = ((const float4*)g_A)[g * NFLOAT4 + c4];
    float4 bv = ((const float4*)g_B)[g * NFLOAT4 + c4];

    float4 ov;
    ov.x = fmaf(xv.x, av.x, bv.x);
    ov.y = fmaf(xv.y, av.y, bv.y);
    ov.z = fmaf(xv.z, av.z, bv.z);
    ov.w = fmaf(xv.w, av.w, bv.w);
    ((float4*)out)[idx] = ov;
}

extern "C" void kernel_launch(void* const* d_in, const int* in_sizes, int n_in,
                              void* d_out, int out_size) {
    const float* x = (const float*)d_in[0];
    const int* batch = (const int*)d_in[1];
    const float* weight = (const float*)d_in[2];
    const float* bias = (const float*)d_in[3];
    float* out = (float*)d_out;

    int n_nodes = in_sizes[1];

    zero_stats_kernel<<<1, N_GRAPHS * 12>>>();

    int n_warps = (n_nodes + NPW - 1) / NPW;
    int threads1 = 256;
    int blocks1 = (n_warps * 32 + threads1 - 1) / threads1;
    stats_kernel<<<blocks1, threads1>>>(x, batch, n_nodes);

    int np = N_GRAPHS * DIMTOT;
    params_kernel<<<(np + 255) / 256, 256>>>(weight, bias);

    int total = n_nodes * NFLOAT4;
    apply_kernel<<<(total + 255) / 256, 256>>>(x, batch, out, n_nodes);
}

// round 4
// speedup vs baseline: 1.0843x; 1.0843x over previous
#include <cuda_runtime.h>
#include <cuda_bf16.h>

#define N_GRAPHS 64
#define DIMTOT   240     // 64*1 + 32*3 + 16*5
#define NFLOAT4  60      // DIMTOT/4
#define EPS      1e-05f
#define NPW      16      // nodes per warp in stats pass

// stats layout per graph: [0]=count, [1]=s0, [2]=ss0, [3..5]=s1[d], [6..10]=s2[d]
__device__ float g_stats[N_GRAPHS][12];   // zero-initialized at load; re-zeroed by apply epilogue
__device__ float g_A[N_GRAPHS * DIMTOT];
__device__ float g_B[N_GRAPHS * DIMTOT];

// ---------------------------------------------------------------------------
// Pass 1: per-graph sums. One warp handles NPW consecutive nodes.
// float4 loads: lane L owns float4 j0=L (cols 4L..4L+3) and j1=L+32
// (cols 128+4L..131+4L, valid L<28).
// Buckets: col<64 -> s0/ss0 ; 64<=col<160 -> s1[(col-64)%3] ; else s2[(col-160)%5]
// ---------------------------------------------------------------------------
__global__ __launch_bounds__(256) void stats_kernel(const float* __restrict__ x,
                                                    const int* __restrict__ batch,
                                                    int n_nodes) {
    const int warp_id = (blockIdx.x * blockDim.x + threadIdx.x) >> 5;
    const int lane = threadIdx.x & 31;
    const int n0 = warp_id * NPW;
    if (n0 >= n_nodes) return;
    const int n1 = min(n0 + NPW, n_nodes);

    // routing tables: target index in v[10] for each float4 component
    // lane<16: sa -> v[0] (+ssq -> v[1]); lane>=16: sa[i] -> v[2 + (4*lane-64+i)%3]
    // lane<8 : sb[i] -> v[2 + (64+4*lane+i)%3]
    // 8<=lane<28: sb[i] -> v[5 + (4*lane-32+i)%5];  lane>=28: sb invalid
    int ta[4], tb[4];
#pragma unroll
    for (int i = 0; i < 4; i++) {
        ta[i] = (lane < 16) ? 0 : 2 + (4 * lane - 64 + i) % 3;
        if (lane < 8)       tb[i] = 2 + (64 + 4 * lane + i) % 3;
        else if (lane < 28) tb[i] = 5 + (4 * lane - 32 + i) % 5;
        else                tb[i] = -1;
    }
    const bool has_b = (lane < 28);
    const bool is_l0 = (lane < 16);

    float sa[4] = {0, 0, 0, 0}, sb[4] = {0, 0, 0, 0}, sq[4] = {0, 0, 0, 0};
    float cnt = 0.0f;

    auto flush = [&](int g) {
        float v[10];
#pragma unroll
        for (int i = 0; i < 10; i++) v[i] = 0.0f;
        if (is_l0) {
            v[0] = sa[0] + sa[1] + sa[2] + sa[3];
            v[1] = sq[0] + sq[1] + sq[2] + sq[3];
        } else {
#pragma unroll
            for (int d = 0; d < 3; d++) {
                float s = 0.0f;
#pragma unroll
                for (int i = 0; i < 4; i++) s += (ta[i] == 2 + d) ? sa[i] : 0.0f;
                v[2 + d] = s;
            }
        }
#pragma unroll
        for (int d = 0; d < 3; d++) {
            float s = 0.0f;
#pragma unroll
            for (int i = 0; i < 4; i++) s += (tb[i] == 2 + d) ? sb[i] : 0.0f;
            v[2 + d] += s;
        }
#pragma unroll
        for (int d = 0; d < 5; d++) {
            float s = 0.0f;
#pragma unroll
            for (int i = 0; i < 4; i++) s += (tb[i] == 5 + d) ? sb[i] : 0.0f;
            v[5 + d] = s;
        }
#pragma unroll
        for (int off = 16; off > 0; off >>= 1) {
#pragma unroll
            for (int i = 0; i < 10; i++)
                v[i] += __shfl_xor_sync(0xFFFFFFFFu, v[i], off);
        }
        if (lane == 0) {
            atomicAdd(&g_stats[g][0], cnt);
#pragma unroll
            for (int i = 0; i < 10; i++)
                atomicAdd(&g_stats[g][1 + i], v[i]);
        }
    };

    const int gfirst = __ldg(&batch[n0]);
    const int glast = __ldg(&batch[n1 - 1]);

    if (gfirst == glast) {
        // fast path: whole range in one graph (~99.5% of warps)
        for (int n = n0; n < n1; n++) {
            const float4* row = (const float4*)(x + (size_t)n * DIMTOT);
            float4 va = __ldg(&row[lane]);
            sa[0] += va.x; sa[1] += va.y; sa[2] += va.z; sa[3] += va.w;
            if (is_l0) {
                sq[0] += va.x * va.x; sq[1] += va.y * va.y;
                sq[2] += va.z * va.z; sq[3] += va.w * va.w;
            }
            if (has_b) {
                float4 vb = __ldg(&row[lane + 32]);
                sb[0] += vb.x; sb[1] += vb.y; sb[2] += vb.z; sb[3] += vb.w;
            }
        }
        cnt = (float)(n1 - n0);
        flush(gfirst);
    } else {
        int cur_g = gfirst;
        for (int n = n0; n < n1; n++) {
            int g = __ldg(&batch[n]);
            if (g != cur_g) {
                flush(cur_g);
#pragma unroll
                for (int i = 0; i < 4; i++) { sa[i] = 0; sb[i] = 0; sq[i] = 0; }
                cnt = 0.0f;
                cur_g = g;
            }
            const float4* row = (const float4*)(x + (size_t)n * DIMTOT);
            float4 va = __ldg(&row[lane]);
            sa[0] += va.x; sa[1] += va.y; sa[2] += va.z; sa[3] += va.w;
            if (is_l0) {
                sq[0] += va.x * va.x; sq[1] += va.y * va.y;
                sq[2] += va.z * va.z; sq[3] += va.w * va.w;
            }
            if (has_b) {
                float4 vb = __ldg(&row[lane + 32]);
                sb[0] += vb.x; sb[1] += vb.y; sb[2] += vb.z; sb[3] += vb.w;
            }
            cnt += 1.0f;
        }
        flush(cur_g);
    }
}

// ---------------------------------------------------------------------------
// Pass 1.5: build per-(graph,column) affine params  out = x*A + B
// ---------------------------------------------------------------------------
__global__ void params_kernel(const float* __restrict__ weight,
                              const float* __restrict__ bias) {
    int idx = blockIdx.x * blockDim.x + threadIdx.x;
    if (idx >= N_GRAPHS * DIMTOT) return;
    int g = idx / DIMTOT;
    int c = idx - g * DIMTOT;

    float cntf = fmaxf(g_stats[g][0], 1.0f);
    float a, b;
    if (c < 64) {
        float inv64 = 1.0f / (cntf * 64.0f);
        float m = g_stats[g][1] * inv64;
        float var = g_stats[g][2] * inv64 - m * m;
        float inv = 1.0f / (sqrtf(fmaxf(var, 0.0f)) + EPS);
        a = weight[c] * inv;
        b = bias[c] - m * a;
    } else if (c < 160) {
        int cc = c - 64;
        int d = cc % 3;
        int mI = cc / 3;
        float mu = g_stats[g][3 + d] / (cntf * 32.0f);
        a = weight[64 + mI];
        b = -mu * a;
    } else {
        int cc = c - 160;
        int d = cc % 5;
        int mI = cc / 5;
        float mu = g_stats[g][6 + d] / (cntf * 16.0f);
        a = weight[96 + mI];
        b = -mu * a;
    }
    g_A[idx] = a;
    g_B[idx] = b;
}

// ---------------------------------------------------------------------------
// Pass 2: streaming affine apply. 2 float4 per thread, blocks process x in
// REVERSE macro-order so the tail of x (still hot in L2 from the stats pass)
// is consumed first. Also re-zeros g_stats for the next graph replay.
// ---------------------------------------------------------------------------
#define APPLY_ITER 2
__global__ __launch_bounds__(256) void apply_kernel(const float* __restrict__ x,
                                                    const int* __restrict__ batch,
                                                    float* __restrict__ out,
                                                    int n_nodes) {
    const int total = n_nodes * NFLOAT4;
    const int rb = gridDim.x - 1 - blockIdx.x;        // reversed block order
    const int base = rb * (256 * APPLY_ITER) + threadIdx.x;

#pragma unroll
    for (int k = 0; k < APPLY_ITER; k++) {
        int idx = base + k * 256;
        if (idx < total) {
            int n = idx / NFLOAT4;
            int c4 = idx - n * NFLOAT4;
            int g = __ldg(&batch[n]);

            float4 xv = __ldg(&((const float4*)x)[idx]);
            float4 av = ((const float4*)g_A)[g * NFLOAT4 + c4];
            float4 bv = ((const float4*)g_B)[g * NFLOAT4 + c4];

            float4 ov;
            ov.x = fmaf(xv.x, av.x, bv.x);
            ov.y = fmaf(xv.y, av.y, bv.y);
            ov.z = fmaf(xv.z, av.z, bv.z);
            ov.w = fmaf(xv.w, av.w, bv.w);
            ((float4*)out)[idx] = ov;
        }
    }

    // epilogue: re-zero stats for the next replay (module-load state is zero,
    // and every run leaves it zero -> deterministic across graph replays)
    if (blockIdx.x == 0 && threadIdx.x < 256) {
        for (int i = threadIdx.x; i < N_GRAPHS * 12; i += 256)
            ((float*)g_stats)[i] = 0.0f;
    }
}

extern "C" void kernel_launch(void* const* d_in, const int* in_sizes, int n_in,
                              void* d_out, int out_size) {
    const float* x = (const float*)d_in[0];
    const int* batch = (const int*)d_in[1];
    const float* weight = (const float*)d_in[2];
    const float* bias = (const float*)d_in[3];
    float* out = (float*)d_out;

    int n_nodes = in_sizes[1];

    int n_warps = (n_nodes + NPW - 1) / NPW;
    int threads1 = 256;
    int blocks1 = (n_warps * 32 + threads1 - 1) / threads1;
    stats_kernel<<<blocks1, threads1>>>(x, batch, n_nodes);

    int np = N_GRAPHS * DIMTOT;
    params_kernel<<<(np + 255) / 256, 256>>>(weight, bias);

    int total = n_nodes * NFLOAT4;
    int blocks2 = (total + 256 * APPLY_ITER - 1) / (256 * APPLY_ITER);
    apply_kernel<<<blocks2, 256>>>(x, batch, out, n_nodes);
}

// round 5
// speedup vs baseline: 1.2115x; 1.1174x over previous
#include <cuda_runtime.h>
#include <cuda_bf16.h>

#define N_GRAPHS 64
#define DIMTOT   240     // 64*1 + 32*3 + 16*5
#define NFLOAT4  60      // DIMTOT/4
#define EPS      1e-05f
#define NPW      16      // nodes per warp in stats pass

// stats layout per graph: [0]=count, [1]=s0, [2]=ss0, [3..5]=s1[d], [6..10]=s2[d]
__device__ float g_stats[N_GRAPHS][12];   // zero at load; re-zeroed by apply epilogue
__device__ float g_A[N_GRAPHS * DIMTOT];
__device__ float g_B[N_GRAPHS * DIMTOT];

// ---------------------------------------------------------------------------
// Pass 1: per-graph sums. One warp handles NPW consecutive nodes.
// Scalar loads: lane L owns columns L+32k, k=0..6 (all lanes) and k=7 (L<16).
// 7.5 independent LDG.32 per node -> high MLP at 1 reg per outstanding load.
// Routing to stat buckets happens only inside flush (graph boundary / end).
// ---------------------------------------------------------------------------
__global__ __launch_bounds__(256) void stats_kernel(const float* __restrict__ x,
                                                    const int* __restrict__ batch,
                                                    int n_nodes) {
    const int warp_id = (blockIdx.x * blockDim.x + threadIdx.x) >> 5;
    const int lane = threadIdx.x & 31;
    const int n0 = warp_id * NPW;
    if (n0 >= n_nodes) return;
    const int n1 = min(n0 + NPW, n_nodes);
    const bool has_k7 = (lane < 16);

    float acc[8];
#pragma unroll
    for (int k = 0; k < 8; k++) acc[k] = 0.0f;
    float accsq = 0.0f;
    float cnt = 0.0f;

    auto flush = [&](int g) {
        float v[10];
#pragma unroll
        for (int i = 0; i < 10; i++) v[i] = 0.0f;
        v[0] = acc[0] + acc[1];
        v[1] = accsq;
        // cols 64..159 -> s1[(c-64)%3]; cols 160..239 -> s2[(c-160)%5]
#pragma unroll
        for (int k = 2; k <= 4; k++) {
            int d = (lane + 32 * k - 64) % 3;
#pragma unroll
            for (int dd = 0; dd < 3; dd++)
                v[2 + dd] += (d == dd) ? acc[k] : 0.0f;
        }
#pragma unroll
        for (int k = 5; k <= 6; k++) {
            int d = (lane + 32 * k - 160) % 5;
#pragma unroll
            for (int dd = 0; dd < 5; dd++)
                v[5 + dd] += (d == dd) ? acc[k] : 0.0f;
        }
        {
            int d = (lane + 64) % 5;   // k=7: col = lane+224
#pragma unroll
            for (int dd = 0; dd < 5; dd++)
                v[5 + dd] += (has_k7 && d == dd) ? acc[7] : 0.0f;
        }
#pragma unroll
        for (int off = 16; off > 0; off >>= 1) {
#pragma unroll
            for (int i = 0; i < 10; i++)
                v[i] += __shfl_xor_sync(0xFFFFFFFFu, v[i], off);
        }
        if (lane == 0) {
            atomicAdd(&g_stats[g][0], cnt);
#pragma unroll
            for (int i = 0; i < 10; i++)
                atomicAdd(&g_stats[g][1 + i], v[i]);
        }
    };

    const int gfirst = __ldg(&batch[n0]);
    const int glast = __ldg(&batch[n1 - 1]);

    if (gfirst == glast) {
        // fast path: whole warp range in one graph (~99.5% of warps)
#pragma unroll 2
        for (int n = n0; n < n1; n++) {
            const float* row = x + (size_t)n * DIMTOT;
            float vv[8];
#pragma unroll
            for (int k = 0; k < 7; k++) vv[k] = __ldg(&row[lane + 32 * k]);
            vv[7] = has_k7 ? __ldg(&row[lane + 224]) : 0.0f;
#pragma unroll
            for (int k = 0; k < 8; k++) acc[k] += vv[k];
            accsq += vv[0] * vv[0] + vv[1] * vv[1];
        }
        cnt = (float)(n1 - n0);
        flush(gfirst);
    } else {
        int cur_g = gfirst;
        for (int n = n0; n < n1; n++) {
            int g = __ldg(&batch[n]);
            if (g != cur_g) {
                flush(cur_g);
#pragma unroll
                for (int k = 0; k < 8; k++) acc[k] = 0.0f;
                accsq = 0.0f;
                cnt = 0.0f;
                cur_g = g;
            }
            const float* row = x + (size_t)n * DIMTOT;
            float vv[8];
#pragma unroll
            for (int k = 0; k < 7; k++) vv[k] = __ldg(&row[lane + 32 * k]);
            vv[7] = has_k7 ? __ldg(&row[lane + 224]) : 0.0f;
#pragma unroll
            for (int k = 0; k < 8; k++) acc[k] += vv[k];
            accsq += vv[0] * vv[0] + vv[1] * vv[1];
            cnt += 1.0f;
        }
        flush(cur_g);
    }
}

// ---------------------------------------------------------------------------
// Pass 1.5: build per-(graph,column) affine params  out = x*A + B
// ---------------------------------------------------------------------------
__global__ void params_kernel(const float* __restrict__ weight,
                              const float* __restrict__ bias) {
    int idx = blockIdx.x * blockDim.x + threadIdx.x;
    if (idx >= N_GRAPHS * DIMTOT) return;
    int g = idx / DIMTOT;
    int c = idx - g * DIMTOT;

    float cntf = fmaxf(g_stats[g][0], 1.0f);
    float a, b;
    if (c < 64) {
        float inv64 = 1.0f / (cntf * 64.0f);
        float m = g_stats[g][1] * inv64;
        float var = g_stats[g][2] * inv64 - m * m;
        float inv = 1.0f / (sqrtf(fmaxf(var, 0.0f)) + EPS);
        a = weight[c] * inv;
        b = bias[c] - m * a;
    } else if (c < 160) {
        int cc = c - 64;
        int d = cc % 3;
        int mI = cc / 3;
        float mu = g_stats[g][3 + d] / (cntf * 32.0f);
        a = weight[64 + mI];
        b = -mu * a;
    } else {
        int cc = c - 160;
        int d = cc % 5;
        int mI = cc / 5;
        float mu = g_stats[g][6 + d] / (cntf * 16.0f);
        a = weight[96 + mI];
        b = -mu * a;
    }
    g_A[idx] = a;
    g_B[idx] = b;
}

// ---------------------------------------------------------------------------
// Pass 2: streaming affine apply. 2 float4 per thread, blocks process x in
// REVERSE macro-order so the tail of x (still hot in L2 from the stats pass)
// is consumed first. Also re-zeros g_stats for the next graph replay.
// ---------------------------------------------------------------------------
#define APPLY_ITER 2
__global__ __launch_bounds__(256) void apply_kernel(const float* __restrict__ x,
                                                    const int* __restrict__ batch,
                                                    float* __restrict__ out,
                                                    int n_nodes) {
    const int total = n_nodes * NFLOAT4;
    const int rb = gridDim.x - 1 - blockIdx.x;        // reversed block order
    const int base = rb * (256 * APPLY_ITER) + threadIdx.x;

#pragma unroll
    for (int k = 0; k < APPLY_ITER; k++) {
        int idx = base + k * 256;
        if (idx < total) {
            int n = idx / NFLOAT4;
            int c4 = idx - n * NFLOAT4;
            int g = __ldg(&batch[n]);

            float4 xv = __ldg(&((const float4*)x)[idx]);
            float4 av = ((const float4*)g_A)[g * NFLOAT4 + c4];
            float4 bv = ((const float4*)g_B)[g * NFLOAT4 + c4];

            float4 ov;
            ov.x = fmaf(xv.x, av.x, bv.x);
            ov.y = fmaf(xv.y, av.y, bv.y);
            ov.z = fmaf(xv.z, av.z, bv.z);
            ov.w = fmaf(xv.w, av.w, bv.w);
            ((float4*)out)[idx] = ov;
        }
    }

    // epilogue: re-zero stats for the next replay (module-load state is zero,
    // and every run leaves it zero -> deterministic across graph replays)
    if (blockIdx.x == 0 && threadIdx.x < 256) {
        for (int i = threadIdx.x; i < N_GRAPHS * 12; i += 256)
            ((float*)g_stats)[i] = 0.0f;
    }
}

extern "C" void kernel_launch(void* const* d_in, const int* in_sizes, int n_in,
                              void* d_out, int out_size) {
    const float* x = (const float*)d_in[0];
    const int* batch = (const int*)d_in[1];
    const float* weight = (const float*)d_in[2];
    const float* bias = (const float*)d_in[3];
    float* out = (float*)d_out;

    int n_nodes = in_sizes[1];

    int n_warps = (n_nodes + NPW - 1) / NPW;
    int threads1 = 256;
    int blocks1 = (n_warps * 32 + threads1 - 1) / threads1;
    stats_kernel<<<blocks1, threads1>>>(x, batch, n_nodes);

    int np = N_GRAPHS * DIMTOT;
    params_kernel<<<(np + 255) / 256, 256>>>(weight, bias);

    int total = n_nodes * NFLOAT4;
    int blocks2 = (total + 256 * APPLY_ITER - 1) / (256 * APPLY_ITER);
    apply_kernel<<<blocks2, 256>>>(x, batch, out, n_nodes);
}